// round 16
// baseline (speedup 1.0000x reference)
#include <cuda_runtime.h>
#include <cuda_bf16.h>
#include <cstdint>

// Problem constants (fixed shapes for TimeWindowBlock_3925600108827)
#define H    64      // hidden
#define FF   36      // MLP hidden
#define SEQ  200     // S
#define NW   8       // W windows
#define KTST 204     // kT row stride (floats): transpose stores + row reads conflict-free
#define MTST 40      // MT row stride (floats)
#define SPST 204     // score-partials row stride

typedef unsigned long long u64;

// -------- mask dtype autodetection (bool may arrive as i32 / f32 / u8) ----
__device__ int g_mask_mode;   // 0 = int32, 1 = float32, 2 = byte

__global__ void detect_mask_kernel(const unsigned int* m, int nwords) {
    __shared__ int s_not01, s_not0f;
    if (threadIdx.x == 0) { s_not01 = 0; s_not0f = 0; }
    __syncthreads();
    int n01 = 0, n0f = 0;
    for (int i = threadIdx.x; i < nwords; i += blockDim.x) {
        unsigned int w = m[i];
        if (w > 1u) n01 = 1;
        if (w != 0u && w != 0x3f800000u) n0f = 1;
    }
    if (n01) s_not01 = 1;
    if (n0f) s_not0f = 1;
    __syncthreads();
    if (threadIdx.x == 0)
        g_mask_mode = (!s_not01) ? 0 : ((!s_not0f) ? 1 : 2);
}

// -------- packed fp32x2 helpers (sm_100+) ----------------------------------
__device__ __forceinline__ u64 ffma2(u64 a, u64 b, u64 c) {
    u64 d;
    asm("fma.rn.f32x2 %0, %1, %2, %3;" : "=l"(d) : "l"(a), "l"(b), "l"(c));
    return d;
}
__device__ __forceinline__ float2 up2(u64 v) {
    float2 r;
    asm("mov.b64 {%0, %1}, %2;" : "=f"(r.x), "=f"(r.y) : "l"(v));
    return r;
}
__device__ __forceinline__ u64 dup2(float f) {
    u64 r;
    asm("mov.b64 %0, {%1, %1};" : "=l"(r) : "f"(f));
    return r;
}

__device__ __forceinline__ float wredmax(float v) {
    #pragma unroll
    for (int o = 16; o; o >>= 1) v = fmaxf(v, __shfl_xor_sync(0xffffffffu, v, o));
    return v;
}
__device__ __forceinline__ float wredsum(float v) {
    #pragma unroll
    for (int o = 16; o; o >>= 1) v += __shfl_xor_sync(0xffffffffu, v, o);
    return v;
}

// Dynamic smem layout (floats):
//  kT     : 64 * 204 = 13056   (k transposed: kT[d][s])
//  MT     : 64 * 40  = 2560    (folded matrix, d-major: MT[d][o])
//  sPart  : 4 * 204  = 816     (per-og score partials)
//  sC     : 40
//  sW2    : 40
//  sQ     : 64
//  sScore : 208
//  sRed   : 32
// total = 16816 floats = 67,264 bytes  (x3 CTAs = 201.8 KB <= 228 KB)
#define SMEM_FLOATS (64*KTST + 64*MTST + 4*SPST + 40 + 40 + 64 + 208 + 32)

__global__ void __launch_bounds__(128, 3)
twb_kernel(const float* __restrict__ query,
           const float* __restrict__ key,
           const float* __restrict__ W1,
           const float* __restrict__ b1,
           const float* __restrict__ prelu_a,
           const float* __restrict__ W2,
           const float* __restrict__ b2,
           const void*  __restrict__ maskp,
           float* __restrict__ out)
{
    extern __shared__ float smem[];
    float* kT     = smem;                       // [64][KTST]
    float* MT     = kT + 64 * KTST;             // [64][MTST]
    float* sPart  = MT + 64 * MTST;             // [4][SPST]
    float* sC     = sPart + 4 * SPST;           // [40]
    float* sW2    = sC + 40;                    // [40]
    float* sQ     = sW2 + 40;                   // [64]
    float* sScore = sQ + 64;                    // [208]
    float* sRed   = sScore + 208;               // [32]

    const int cta  = blockIdx.x;                // b*NW + w
    const int b    = cta >> 3;                  // NW == 8
    const int tid  = threadIdx.x;
    const int lane = tid & 31;
    const int wid5 = tid >> 5;

    // ---- Phase 0: q row ---------------------------------------------------
    if (tid < H) sQ[tid] = query[b * H + tid];
    __syncthreads();

    // ---- Phase 1: k (global row-major) -> kT (smem transposed) ------------
    // conflict-free: consecutive lanes -> consecutive s within a d row
    {
        const float4* kg = reinterpret_cast<const float4*>(key + (size_t)cta * SEQ * H);
        for (int i = tid; i < SEQ * (H / 4); i += 128) {
            int pair = i >> 1, sub = i & 1;
            int s   = pair % SEQ;
            int c4  = (pair / SEQ) * 2 + sub;       // 0..15
            float4 v = kg[s * (H / 4) + c4];
            int d0 = c4 * 4;
            kT[(d0 + 0) * KTST + s] = v.x;
            kT[(d0 + 1) * KTST + s] = v.y;
            kT[(d0 + 2) * KTST + s] = v.z;
            kT[(d0 + 3) * KTST + s] = v.w;
        }
    }

    // ---- Phase 2: MT[d][o] = W1b - W1c + W1d*q[d] ; sC ; sW2 --------------
    for (int i = tid; i < FF * H; i += 128) {
        int o = i % FF, d = i / FF;
        const float* w1r = W1 + o * (4 * H);
        MT[d * MTST + o] = w1r[64 + d] - w1r[128 + d] + w1r[192 + d] * sQ[d];
    }
    if (tid < FF) {
        const float* w1r = W1 + tid * (4 * H);
        float a0 = b1[tid], a1 = 0.f, a2 = 0.f, a3 = 0.f;
        #pragma unroll 4
        for (int d = 0; d < H; d += 4) {
            a0 = fmaf(w1r[d + 0] + w1r[128 + d + 0], sQ[d + 0], a0);
            a1 = fmaf(w1r[d + 1] + w1r[128 + d + 1], sQ[d + 1], a1);
            a2 = fmaf(w1r[d + 2] + w1r[128 + d + 2], sQ[d + 2], a2);
            a3 = fmaf(w1r[d + 3] + w1r[128 + d + 3], sQ[d + 3], a3);
        }
        sC[tid]  = (a0 + a1) + (a2 + a3);
        sW2[tid] = W2[tid];
    }
    __syncthreads();

    const float pa  = prelu_a[0];
    const float b2v = b2[0];

    // ---- Phase 3: tiled GEMM, 8s (4 adjacent pairs @ stride 50) x 9o ------
    // thread t<100: sg = t%25, og = t/25.  s-pairs: (2sg+50i, 2sg+1+50i)
    // k-fragment: LDS.64 at u64 index sg+25i -> consecutive lanes,
    //             consecutive even banks -> conflict-free, 100% useful bytes.
    // m: scalar LDS.32 broadcast (minimal return BW) + ALU dup.
    if (tid < 100) {
        const int sg = tid % 25, og = tid / 25;
        const int o0 = og * 9;

        u64 acc[4][9];
        #pragma unroll
        for (int i = 0; i < 4; i++)
            #pragma unroll
            for (int j = 0; j < 9; j++) acc[i][j] = 0ull;

        #pragma unroll 2
        for (int d = 0; d < H; d++) {
            const u64* krow = reinterpret_cast<const u64*>(kT + d * KTST);
            u64 k0 = krow[sg];
            u64 k1 = krow[sg + 25];
            u64 k2 = krow[sg + 50];
            u64 k3 = krow[sg + 75];
            const float* mrow = MT + d * MTST + o0;
            #pragma unroll
            for (int j = 0; j < 9; j++) {
                u64 md = dup2(mrow[j]);
                acc[0][j] = ffma2(k0, md, acc[0][j]);
                acc[1][j] = ffma2(k1, md, acc[1][j]);
                acc[2][j] = ffma2(k2, md, acc[2][j]);
                acc[3][j] = ffma2(k3, md, acc[3][j]);
            }
        }

        // epilogue: h complete per-thread -> PReLU -> W2 dot -> partials
        float spl[8];
        #pragma unroll
        for (int i = 0; i < 8; i++) spl[i] = 0.f;
        #pragma unroll
        for (int j = 0; j < 9; j++) {
            int o = o0 + j;
            float c = sC[o], w2 = sW2[o];
            #pragma unroll
            for (int i = 0; i < 4; i++) {
                float2 f = up2(acc[i][j]);
                float h0 = f.x + c; h0 = (h0 >= 0.f) ? h0 : pa * h0;
                float h1 = f.y + c; h1 = (h1 >= 0.f) ? h1 : pa * h1;
                spl[2 * i]     = fmaf(w2, h0, spl[2 * i]);
                spl[2 * i + 1] = fmaf(w2, h1, spl[2 * i + 1]);
            }
        }
        #pragma unroll
        for (int i = 0; i < 4; i++) {
            float2* dst = reinterpret_cast<float2*>(sPart + og * SPST + 2 * sg + 50 * i);
            *dst = make_float2(spl[2 * i], spl[2 * i + 1]);
        }
    }
    __syncthreads();

    // ---- Phase 4: combine partials, mask, softmax over SEQ ----------------
    float v0, v1;
    {
        int mode = g_mask_mode;
        // s = tid
        float sc = b2v + ((sPart[tid] + sPart[SPST + tid])
                        + (sPart[2 * SPST + tid] + sPart[3 * SPST + tid]));
        size_t mi = (size_t)cta * SEQ + tid;
        bool mk;
        if (mode == 0)      mk = ((const int*)maskp)[mi] != 0;
        else if (mode == 1) mk = ((const float*)maskp)[mi] != 0.0f;
        else                mk = ((const unsigned char*)maskp)[mi] != 0;
        v0 = mk ? -10000.0f : sc;
        // s = tid + 128 (if valid)
        v1 = -1e30f;
        if (tid + 128 < SEQ) {
            int s = tid + 128;
            float sc1 = b2v + ((sPart[s] + sPart[SPST + s])
                             + (sPart[2 * SPST + s] + sPart[3 * SPST + s]));
            size_t mi1 = (size_t)cta * SEQ + s;
            bool mk1;
            if (mode == 0)      mk1 = ((const int*)maskp)[mi1] != 0;
            else if (mode == 1) mk1 = ((const float*)maskp)[mi1] != 0.0f;
            else                mk1 = ((const unsigned char*)maskp)[mi1] != 0;
            v1 = mk1 ? -10000.0f : sc1;
        }
    }

    float wm = wredmax(fmaxf(v0, v1));
    if (lane == 0) sRed[wid5] = wm;
    __syncthreads();
    float mx = fmaxf(fmaxf(sRed[0], sRed[1]), fmaxf(sRed[2], sRed[3]));
    __syncthreads();                       // before sRed reuse

    float e0 = __expf(v0 - mx);
    float e1 = (tid + 128 < SEQ) ? __expf(v1 - mx) : 0.0f;
    sScore[tid] = e0;
    if (tid + 128 < SEQ) sScore[tid + 128] = e1;
    float ws = wredsum(e0 + e1);
    if (lane == 0) sRed[wid5] = ws;
    __syncthreads();                       // orders sScore writes for phase 5
    float sum = (sRed[0] + sRed[1]) + (sRed[2] + sRed[3]);
    float inv = 1.0f / sum;

    // ---- Phase 5: out[d] = inv * sum_s e_s * kT[d][s] ----------------------
    // warp w handles d = w*16 .. w*16+15; lanes stride over s (contiguous row)
    #pragma unroll
    for (int rep = 0; rep < 16; rep++) {
        int d = wid5 * 16 + rep;
        const float* kr = kT + d * KTST;
        float a = 0.f;
        #pragma unroll 7
        for (int s = lane; s < SEQ; s += 32)
            a = fmaf(sScore[s], kr[s], a);
        a = wredsum(a);
        if (lane == 0) out[(size_t)cta * H + d] = a * inv;
    }
}

extern "C" void kernel_launch(void* const* d_in, const int* in_sizes, int n_in,
                              void* d_out, int out_size) {
    const float* query = (const float*)d_in[0];
    const float* key   = (const float*)d_in[1];
    const float* W1    = (const float*)d_in[2];
    const float* b1    = (const float*)d_in[3];
    const float* pa    = (const float*)d_in[4];
    const float* W2    = (const float*)d_in[5];
    const float* b2    = (const float*)d_in[6];
    const void*  mask  = d_in[7];
    float* out = (float*)d_out;

    int n_bw = in_sizes[1] / (SEQ * H);    // B*W (= 4096)

    detect_mask_kernel<<<1, 256>>>((const unsigned int*)mask, 4096);

    const int smem_bytes = SMEM_FLOATS * (int)sizeof(float);
    cudaFuncSetAttribute(twb_kernel,
                         cudaFuncAttributeMaxDynamicSharedMemorySize,
                         smem_bytes);
    twb_kernel<<<n_bw, 128, smem_bytes>>>(query, key, W1, b1, pa, W2, b2,
                                          mask, out);
}